// round 14
// baseline (speedup 1.0000x reference)
#include <cuda_runtime.h>
#include <cstdint>
#include <math.h>

#define Bb   4
#define Tt   8192
#define Dd   1024
#define Ff   4096
#define CAP  4096
#define MTOT (Bb*CAP)   // 16384 selected tokens

// ---------------- scratch (device globals: allocation-free rule) ------------
__device__ float g_scores[Bb*Tt];
__device__ int   g_sel[MTOT];
__device__ __align__(16) float g_xg[(size_t)MTOT * (size_t)Dd];   // gathered+rounded x (64MB)
__device__ __align__(16) float g_h [(size_t)MTOT * (size_t)Ff];   // hidden, tf32-rounded (256MB)
__device__ __align__(16) float g_w1t[(size_t)Ff * (size_t)Dd];    // w1^T rounded [F][D] (16MB)
__device__ __align__(16) float g_w2t[(size_t)Dd * (size_t)Ff];    // w2^T rounded [D][F] (16MB)

// ---------------------------------------------------------------------------
__device__ __forceinline__ unsigned cvt_tf32(float f) {
    unsigned u; asm("cvt.rna.tf32.f32 %0, %1;" : "=r"(u) : "f"(f)); return u;
}
__device__ __forceinline__ float rnd_tf32(float f) { return __uint_as_float(cvt_tf32(f)); }
__device__ __forceinline__ uint32_t smem_u32(const void* p) {
    uint32_t a;
    asm("{ .reg .u64 t; cvta.to.shared.u64 t, %1; cvt.u32.u64 %0, t; }" : "=r"(a) : "l"(p));
    return a;
}
__device__ __forceinline__ void cp16(uint32_t dst, const float* src) {
    asm volatile("cp.async.cg.shared.global [%0], [%1], 16;" :: "r"(dst), "l"(src) : "memory");
}
#define CP_COMMIT() asm volatile("cp.async.commit_group;" ::: "memory")
#define CP_WAIT1()  asm volatile("cp.async.wait_group 1;" ::: "memory")

__device__ __forceinline__ void ldsm4(unsigned* r, uint32_t addr) {
    asm volatile("ldmatrix.sync.aligned.m8n8.x4.shared.b16 {%0,%1,%2,%3}, [%4];"
                 : "=r"(r[0]), "=r"(r[1]), "=r"(r[2]), "=r"(r[3]) : "r"(addr));
}
__device__ __forceinline__ void mma8(float* d, const unsigned* a, const unsigned* b) {
    asm volatile(
        "mma.sync.aligned.m16n8k8.row.col.f32.tf32.tf32.f32 "
        "{%0,%1,%2,%3},{%4,%5,%6,%7},{%8,%9},{%0,%1,%2,%3};\n"
        : "+f"(d[0]), "+f"(d[1]), "+f"(d[2]), "+f"(d[3])
        : "r"(a[0]), "r"(a[1]), "r"(a[2]), "r"(a[3]), "r"(b[0]), "r"(b[1]));
}
__device__ __forceinline__ float gelu_t(float x) {   // jax gelu approximate=True
    float u = 0.7978845608028654f * (x + 0.044715f * x * x * x);
    return 0.5f * x * (1.0f + tanhf(u));
}

// ---------------------------------------------------------------------------
// Kernel 1: router scores (one warp per token) fused with passthrough copy
// ---------------------------------------------------------------------------
__global__ void scores_copy_kernel(const float* __restrict__ x,
                                   const float* __restrict__ wr,
                                   float* __restrict__ out)
{
    int gw   = (blockIdx.x * blockDim.x + threadIdx.x) >> 5;
    int lane = threadIdx.x & 31;
    const float* xr   = x   + (size_t)gw * Dd;
    float*       orow = out + (size_t)gw * Dd;
    float s = 0.f;
    #pragma unroll
    for (int i = 0; i < Dd; i += 128) {
        float4 a = *(const float4*)(xr + i + lane*4);
        float4 w = *(const float4*)(wr + i + lane*4);
        *(float4*)(orow + i + lane*4) = a;          // passthrough copy
        s += a.x*w.x; s += a.y*w.y; s += a.z*w.z; s += a.w*w.w;
    }
    #pragma unroll
    for (int o = 16; o; o >>= 1) s += __shfl_xor_sync(0xffffffffu, s, o);
    if (lane == 0) g_scores[gw] = s;
}

// ---------------------------------------------------------------------------
// Kernel 2: per-row top-CAP radix select (ties lowest-index-first)
// ---------------------------------------------------------------------------
__global__ void select_kernel()
{
    __shared__ unsigned keys[Tt];
    __shared__ int      hist[256];
    __shared__ int      wsum[32];
    __shared__ unsigned s_prefix;
    __shared__ int      s_k, s_cnt, s_pos;

    const int b = blockIdx.x;
    const int t = threadIdx.x;
    const int lane = t & 31, wid = t >> 5;

    for (int i = t; i < Tt; i += 1024) {
        unsigned u = __float_as_uint(g_scores[b*Tt + i]);
        u = (u & 0x80000000u) ? ~u : (u | 0x80000000u);
        keys[i] = u;
    }
    if (t == 0) { s_prefix = 0u; s_k = CAP; }
    __syncthreads();

    for (int shift = 24; shift >= 0; shift -= 8) {
        if (t < 256) hist[t] = 0;
        __syncthreads();
        unsigned hi  = (shift == 24) ? 0u : (0xFFFFFFFFu << (shift + 8));
        unsigned pfx = s_prefix;
        for (int i = t; i < Tt; i += 1024) {
            unsigned k = keys[i];
            if ((k & hi) == pfx) atomicAdd(&hist[(k >> shift) & 255], 1);
        }
        __syncthreads();
        if (t == 0) {
            int k = s_k, bin;
            for (bin = 255; bin > 0; bin--) {
                int c = hist[bin];
                if (c >= k) break;
                k -= c;
            }
            s_prefix |= ((unsigned)bin) << shift;
            s_k = k;
        }
        __syncthreads();
    }
    const unsigned thresh = s_prefix;

    if (t == 0) { s_cnt = 0; s_pos = 0; }
    __syncthreads();
    int loc = 0;
    for (int i = t; i < Tt; i += 1024) if (keys[i] > thresh) loc++;
    atomicAdd(&s_cnt, loc);
    __syncthreads();
    const int greater = s_cnt;
    const int need    = CAP - greater;

    for (int i = t; i < Tt; i += 1024)
        if (keys[i] > thresh) { int p = atomicAdd(&s_pos, 1); g_sel[b*CAP + p] = i; }

    // ties: index-ordered; exclusive prefix via shfl warp scan + cross-warp scan
    int cnt = 0;
    #pragma unroll
    for (int j = 0; j < 8; j++) if (keys[t*8 + j] == thresh) cnt++;
    int v = cnt;
    #pragma unroll
    for (int o = 1; o < 32; o <<= 1) {
        int u = __shfl_up_sync(0xffffffffu, v, o);
        if (lane >= o) v += u;
    }
    if (lane == 31) wsum[wid] = v;
    __syncthreads();
    if (wid == 0) {
        int s = wsum[lane];
        #pragma unroll
        for (int o = 1; o < 32; o <<= 1) {
            int u = __shfl_up_sync(0xffffffffu, s, o);
            if (lane >= o) s += u;
        }
        wsum[lane] = s;
    }
    __syncthreads();
    int base = (wid > 0) ? wsum[wid - 1] : 0;
    int r = base + v - cnt;
    #pragma unroll
    for (int j = 0; j < 8; j++) {
        int i = t*8 + j;
        if (keys[i] == thresh) {
            if (r < need) g_sel[b*CAP + greater + r] = i;
            r++;
        }
    }
}

// ---------------------------------------------------------------------------
// Kernel 3: FUSED prep: gather+round selected rows AND both weight transposes
// ---------------------------------------------------------------------------
#define W1_TILES ((Dd/32)*(Ff/32))   // 4096
#define W2_TILES ((Ff/32)*(Dd/32))   // 4096

__global__ void prep_kernel(const float* __restrict__ x,
                            const float* __restrict__ w1,
                            const float* __restrict__ w2)
{
    int blk = blockIdx.x;
    if (blk < MTOT) {
        int row = blk;
        int bb  = row >> 12;
        int tok = g_sel[row];
        const float4* src = (const float4*)(x + (size_t)(bb*Tt + tok) * Dd);
        float4*       dst = (float4*)(g_xg + (size_t)row * Dd);
        float4 v = src[threadIdx.x];
        v.x = rnd_tf32(v.x); v.y = rnd_tf32(v.y);
        v.z = rnd_tf32(v.z); v.w = rnd_tf32(v.w);
        dst[threadIdx.x] = v;
        return;
    }
    __shared__ float tbuf[32][33];
    int tile = blk - MTOT;
    const float* in; float* outp; int R, C, bx, by;
    if (tile < W1_TILES) {               // w1 [Dd][Ff] -> g_w1t [Ff][Dd]
        in = w1; R = Dd; C = Ff;
        bx = (tile % (Ff/32)) * 32; by = (tile / (Ff/32)) * 32;
        outp = g_w1t;
    } else {                             // w2 [Ff][Dd] -> g_w2t [Dd][Ff]
        tile -= W1_TILES;
        in = w2; R = Ff; C = Dd;
        bx = (tile % (Dd/32)) * 32; by = (tile / (Dd/32)) * 32;
        outp = g_w2t;
    }
    int xt = threadIdx.x & 31, yt = threadIdx.x >> 5;
    #pragma unroll
    for (int j = 0; j < 32; j += 8)
        tbuf[yt + j][xt] = in[(size_t)(by + yt + j) * C + bx + xt];
    __syncthreads();
    #pragma unroll
    for (int j = 0; j < 32; j += 8)
        outp[(size_t)(bx + yt + j) * R + by + xt] = rnd_tf32(tbuf[xt][yt + j]);
}

// ---------------------------------------------------------------------------
// tf32 mma.sync GEMM, 128x128 tiles, BK=16, 4 warps/CTA, warptile 64x64,
// THREE-stage cp.async (20.5KB/stage, 61.4KB total -> 3 CTAs/SM), single
// barrier per iteration (refill target (kt+2)%3 was consumed at kt-1, which
// the top barrier orders). All fragments via ldmatrix.x4; stride 20 floats:
// 8-row LDSM phase starts at banks {0,20,8,28,16,4,24,12}, each 4 wide ->
// all 32 banks exactly once, conflict-free.
// PH1: g_h = tf32(gelu(g_xg @ w1t^T + b1))    (KD=1024, ND=4096)
// PH2: scatter(out) = g_h @ w2t^T + b2        (KD=4096, ND=1024)
// ---------------------------------------------------------------------------
#define BM  128
#define BN  128
#define BK  16
#define AST 20                                 // stride (floats), A and B tiles
#define STG_FLOATS (BM*AST + BN*AST)           // 5120 floats / stage
#define STG_BYTES  (STG_FLOATS * 4)            // 20480 B
#define SMEM_BYTES (3 * STG_BYTES)             // 61440 B -> 3 CTAs/SM

template<int KD, int ND, bool PH1>
__global__ void __launch_bounds__(128, 3)
gemm_tf32(const float* __restrict__ A,      // pre-rounded, row-major [rows][KD]
          const float* __restrict__ Bt,     // pre-rounded W^T, row-major [ND][KD]
          const float* __restrict__ bias,
          float* __restrict__ C)
{
    extern __shared__ float sm[];
    const uint32_t smb = smem_u32(sm);
    const int tid  = threadIdx.x;
    const int warp = tid >> 5, lane = tid & 31;
    const int m0   = blockIdx.y * BM;
    const int n0   = blockIdx.x * BN;

    // staging: per stage, A = 512 float4 (4/thread), B = 512 float4 (4/thread)
    // thread -> row = (tid>>2) + 32j, col = (tid&3)*4
    const float* abase = A  + (size_t)(m0 + (tid >> 2)) * KD + ((tid & 3) << 2);
    const float* bbase = Bt + (size_t)(n0 + (tid >> 2)) * KD + ((tid & 3) << 2);
    const uint32_t adst = smb + (uint32_t)((tid >> 2)*AST + ((tid & 3) << 2)) * 4;
    const uint32_t bdst = adst + (uint32_t)(BM*AST) * 4;

    const int wm = (warp >> 1) * 64, wn = (warp & 1) * 64;

    const int arow_off = (lane & 7) + ((lane >> 3) & 1) * 8;
    const int acol_off = (lane >> 4) * 4;
    uint32_t afrag[4];
    #pragma unroll
    for (int mt = 0; mt < 4; mt++)
        afrag[mt] = smb + (uint32_t)((wm + mt*16 + arow_off)*AST + acol_off) * 4;

    const int brow_off = (lane & 7) + ((lane >> 4) & 1) * 8;
    const int bcol_off = ((lane >> 3) & 1) * 4;
    uint32_t bfrag[4];
    #pragma unroll
    for (int p = 0; p < 4; p++)
        bfrag[p] = smb + (uint32_t)(BM*AST + (wn + p*16 + brow_off)*AST + bcol_off) * 4;

    float acc[4][8][4];
    #pragma unroll
    for (int i = 0; i < 4; i++)
        #pragma unroll
        for (int jn = 0; jn < 8; jn++)
            #pragma unroll
            for (int q = 0; q < 4; q++) acc[i][jn][q] = 0.f;

    const int nk = KD / BK;

    // prologue: issue tiles 0, 1 into buffers 0, 1
    #pragma unroll
    for (int p = 0; p < 2; p++) {
        uint32_t bo = (uint32_t)p * STG_BYTES;
        #pragma unroll
        for (int j = 0; j < 4; j++)
            cp16(adst + bo + (uint32_t)(j*32*AST)*4, abase + p*BK + (size_t)j*32*KD);
        #pragma unroll
        for (int j = 0; j < 4; j++)
            cp16(bdst + bo + (uint32_t)(j*32*AST)*4, bbase + p*BK + (size_t)j*32*KD);
        CP_COMMIT();
    }

    for (int kt = 0; kt < nk; kt++) {
        CP_WAIT1();            // tile kt complete (tile kt+1 may be in flight)
        __syncthreads();       // data visible; also orders buf (kt+2)%3 reuse
                               // (consumed at iter kt-1, before this barrier)

        const uint32_t bufo = (uint32_t)(kt % 3) * STG_BYTES;

        #pragma unroll
        for (int k8 = 0; k8 < BK; k8 += 8) {
            unsigned af[4][4];
            #pragma unroll
            for (int mt = 0; mt < 4; mt++)
                ldsm4(af[mt], afrag[mt] + bufo + (uint32_t)k8 * 4);

            #pragma unroll
            for (int p = 0; p < 4; p++) {          // p covers n-tiles 2p, 2p+1
                unsigned bb[4];
                ldsm4(bb, bfrag[p] + bufo + (uint32_t)k8 * 4);
                #pragma unroll
                for (int mt = 0; mt < 4; mt++)
                    mma8(acc[mt][2*p + 0], af[mt], bb + 0);
                #pragma unroll
                for (int mt = 0; mt < 4; mt++)
                    mma8(acc[mt][2*p + 1], af[mt], bb + 2);
            }
        }

        // refill buffer (kt+2)%3 with tile kt+2 (no second barrier needed)
        if (kt + 2 < nk) {
            uint32_t bo = (uint32_t)((kt + 2) % 3) * STG_BYTES;
            int kofs = (kt + 2) * BK;
            #pragma unroll
            for (int j = 0; j < 4; j++)
                cp16(adst + bo + (uint32_t)(j*32*AST)*4, abase + kofs + (size_t)j*32*KD);
            #pragma unroll
            for (int j = 0; j < 4; j++)
                cp16(bdst + bo + (uint32_t)(j*32*AST)*4, bbase + kofs + (size_t)j*32*KD);
        }
        CP_COMMIT();           // uniform group bookkeeping
    }

    // epilogue: bias (+gelu+round for PH1); PH1 linear store, PH2 scatter
    #pragma unroll
    for (int mt = 0; mt < 4; mt++) {
        #pragma unroll
        for (int half = 0; half < 2; half++) {
            int row = m0 + wm + mt*16 + (lane >> 2) + half*8;
            size_t ob;
            if (PH1) ob = (size_t)row * ND;
            else { int bb2 = row >> 12; ob = ((size_t)(bb2*Tt + g_sel[row])) * (size_t)ND; }
            #pragma unroll
            for (int nt = 0; nt < 8; nt++) {
                int col = n0 + wn + nt*8 + (lane & 3)*2;
                float v0 = acc[mt][nt][half*2 + 0] + bias[col];
                float v1 = acc[mt][nt][half*2 + 1] + bias[col + 1];
                if (PH1) { v0 = rnd_tf32(gelu_t(v0)); v1 = rnd_tf32(gelu_t(v1)); }
                *(float2*)(C + ob + col) = make_float2(v0, v1);
            }
        }
    }
}

// ---------------------------------------------------------------------------
extern "C" void kernel_launch(void* const* d_in, const int* in_sizes, int n_in,
                              void* d_out, int out_size)
{
    const float* x  = (const float*)d_in[0];
    const float* wr = (const float*)d_in[1];
    const float* w1 = (const float*)d_in[2];
    const float* b1 = (const float*)d_in[3];
    const float* w2 = (const float*)d_in[4];
    const float* b2 = (const float*)d_in[5];
    float* out = (float*)d_out;

    float* xg;  cudaGetSymbolAddress((void**)&xg,  g_xg);
    float* h;   cudaGetSymbolAddress((void**)&h,   g_h);
    float* w1t; cudaGetSymbolAddress((void**)&w1t, g_w1t);
    float* w2t; cudaGetSymbolAddress((void**)&w2t, g_w2t);

    scores_copy_kernel<<<(Bb*Tt)/8, 256>>>(x, wr, out);
    select_kernel<<<Bb, 1024>>>();
    prep_kernel<<<MTOT + W1_TILES + W2_TILES, 256>>>(x, w1, w2);

    cudaFuncSetAttribute(gemm_tf32<Dd, Ff, true>,
                         cudaFuncAttributeMaxDynamicSharedMemorySize, SMEM_BYTES);
    cudaFuncSetAttribute(gemm_tf32<Ff, Dd, false>,
                         cudaFuncAttributeMaxDynamicSharedMemorySize, SMEM_BYTES);
    dim3 g1(Ff/BN, MTOT/BM);   // 32 x 128
    dim3 g2(Dd/BN, MTOT/BM);   //  8 x 128
    gemm_tf32<Dd, Ff, true ><<<g1, 128, SMEM_BYTES>>>(xg, w1t, b1, h);
    gemm_tf32<Ff, Dd, false><<<g2, 128, SMEM_BYTES>>>(h,  w2t, b2, out);
}

// round 15
// speedup vs baseline: 1.1259x; 1.1259x over previous
#include <cuda_runtime.h>
#include <cstdint>
#include <math.h>

#define Bb   4
#define Tt   8192
#define Dd   1024
#define Ff   4096
#define CAP  4096
#define MTOT (Bb*CAP)   // 16384 selected tokens

// ---------------- scratch (device globals: allocation-free rule) ------------
__device__ float g_scores[Bb*Tt];
__device__ int   g_sel[MTOT];
__device__ __align__(16) float g_xg[(size_t)MTOT * (size_t)Dd];   // gathered+rounded x (64MB)
__device__ __align__(16) float g_h [(size_t)MTOT * (size_t)Ff];   // hidden, tf32-rounded (256MB)
__device__ __align__(16) float g_w1t[(size_t)Ff * (size_t)Dd];    // w1^T rounded [F][D] (16MB)
__device__ __align__(16) float g_w2t[(size_t)Dd * (size_t)Ff];    // w2^T rounded [D][F] (16MB)

// ---------------------------------------------------------------------------
__device__ __forceinline__ unsigned cvt_tf32(float f) {
    unsigned u; asm("cvt.rna.tf32.f32 %0, %1;" : "=r"(u) : "f"(f)); return u;
}
__device__ __forceinline__ float rnd_tf32(float f) { return __uint_as_float(cvt_tf32(f)); }
__device__ __forceinline__ uint32_t smem_u32(const void* p) {
    uint32_t a;
    asm("{ .reg .u64 t; cvta.to.shared.u64 t, %1; cvt.u32.u64 %0, t; }" : "=r"(a) : "l"(p));
    return a;
}
__device__ __forceinline__ void cp16(uint32_t dst, const float* src) {
    asm volatile("cp.async.cg.shared.global [%0], [%1], 16;" :: "r"(dst), "l"(src) : "memory");
}
#define CP_COMMIT() asm volatile("cp.async.commit_group;" ::: "memory")
#define CP_WAIT1()  asm volatile("cp.async.wait_group 1;" ::: "memory")

__device__ __forceinline__ void ldsm4(unsigned* r, uint32_t addr) {
    asm volatile("ldmatrix.sync.aligned.m8n8.x4.shared.b16 {%0,%1,%2,%3}, [%4];"
                 : "=r"(r[0]), "=r"(r[1]), "=r"(r[2]), "=r"(r[3]) : "r"(addr));
}
__device__ __forceinline__ void mma8(float* d, const unsigned* a, const unsigned* b) {
    asm volatile(
        "mma.sync.aligned.m16n8k8.row.col.f32.tf32.tf32.f32 "
        "{%0,%1,%2,%3},{%4,%5,%6,%7},{%8,%9},{%0,%1,%2,%3};\n"
        : "+f"(d[0]), "+f"(d[1]), "+f"(d[2]), "+f"(d[3])
        : "r"(a[0]), "r"(a[1]), "r"(a[2]), "r"(a[3]), "r"(b[0]), "r"(b[1]));
}
__device__ __forceinline__ float gelu_t(float x) {   // jax gelu approximate=True
    float u = 0.7978845608028654f * (x + 0.044715f * x * x * x);
    return 0.5f * x * (1.0f + tanhf(u));
}

// ---------------------------------------------------------------------------
// Kernel 1: router scores (one warp per token) fused with passthrough copy
// ---------------------------------------------------------------------------
__global__ void scores_copy_kernel(const float* __restrict__ x,
                                   const float* __restrict__ wr,
                                   float* __restrict__ out)
{
    int gw   = (blockIdx.x * blockDim.x + threadIdx.x) >> 5;
    int lane = threadIdx.x & 31;
    const float* xr   = x   + (size_t)gw * Dd;
    float*       orow = out + (size_t)gw * Dd;
    float s = 0.f;
    #pragma unroll
    for (int i = 0; i < Dd; i += 128) {
        float4 a = *(const float4*)(xr + i + lane*4);
        float4 w = *(const float4*)(wr + i + lane*4);
        *(float4*)(orow + i + lane*4) = a;          // passthrough copy
        s += a.x*w.x; s += a.y*w.y; s += a.z*w.z; s += a.w*w.w;
    }
    #pragma unroll
    for (int o = 16; o; o >>= 1) s += __shfl_xor_sync(0xffffffffu, s, o);
    if (lane == 0) g_scores[gw] = s;
}

// ---------------------------------------------------------------------------
// Kernel 2: per-row top-CAP radix select (ties lowest-index-first)
// tie-rank scan via shfl warp scans (2 barriers)
// ---------------------------------------------------------------------------
__global__ void select_kernel()
{
    __shared__ unsigned keys[Tt];
    __shared__ int      hist[256];
    __shared__ int      wsum[32];
    __shared__ unsigned s_prefix;
    __shared__ int      s_k, s_cnt, s_pos;

    const int b = blockIdx.x;
    const int t = threadIdx.x;
    const int lane = t & 31, wid = t >> 5;

    for (int i = t; i < Tt; i += 1024) {
        unsigned u = __float_as_uint(g_scores[b*Tt + i]);
        u = (u & 0x80000000u) ? ~u : (u | 0x80000000u);
        keys[i] = u;
    }
    if (t == 0) { s_prefix = 0u; s_k = CAP; }
    __syncthreads();

    for (int shift = 24; shift >= 0; shift -= 8) {
        if (t < 256) hist[t] = 0;
        __syncthreads();
        unsigned hi  = (shift == 24) ? 0u : (0xFFFFFFFFu << (shift + 8));
        unsigned pfx = s_prefix;
        for (int i = t; i < Tt; i += 1024) {
            unsigned k = keys[i];
            if ((k & hi) == pfx) atomicAdd(&hist[(k >> shift) & 255], 1);
        }
        __syncthreads();
        if (t == 0) {
            int k = s_k, bin;
            for (bin = 255; bin > 0; bin--) {
                int c = hist[bin];
                if (c >= k) break;
                k -= c;
            }
            s_prefix |= ((unsigned)bin) << shift;
            s_k = k;
        }
        __syncthreads();
    }
    const unsigned thresh = s_prefix;

    if (t == 0) { s_cnt = 0; s_pos = 0; }
    __syncthreads();
    int loc = 0;
    for (int i = t; i < Tt; i += 1024) if (keys[i] > thresh) loc++;
    atomicAdd(&s_cnt, loc);
    __syncthreads();
    const int greater = s_cnt;
    const int need    = CAP - greater;

    for (int i = t; i < Tt; i += 1024)
        if (keys[i] > thresh) { int p = atomicAdd(&s_pos, 1); g_sel[b*CAP + p] = i; }

    int cnt = 0;
    #pragma unroll
    for (int j = 0; j < 8; j++) if (keys[t*8 + j] == thresh) cnt++;
    int v = cnt;
    #pragma unroll
    for (int o = 1; o < 32; o <<= 1) {
        int u = __shfl_up_sync(0xffffffffu, v, o);
        if (lane >= o) v += u;
    }
    if (lane == 31) wsum[wid] = v;
    __syncthreads();
    if (wid == 0) {
        int s = wsum[lane];
        #pragma unroll
        for (int o = 1; o < 32; o <<= 1) {
            int u = __shfl_up_sync(0xffffffffu, s, o);
            if (lane >= o) s += u;
        }
        wsum[lane] = s;
    }
    __syncthreads();
    int base = (wid > 0) ? wsum[wid - 1] : 0;
    int r = base + v - cnt;
    #pragma unroll
    for (int j = 0; j < 8; j++) {
        int i = t*8 + j;
        if (keys[i] == thresh) {
            if (r < need) g_sel[b*CAP + greater + r] = i;
            r++;
        }
    }
}

// ---------------------------------------------------------------------------
// Kernel 3: FUSED prep: gather+round selected rows AND both weight transposes
// ---------------------------------------------------------------------------
#define W1_TILES ((Dd/32)*(Ff/32))   // 4096
#define W2_TILES ((Ff/32)*(Dd/32))   // 4096

__global__ void prep_kernel(const float* __restrict__ x,
                            const float* __restrict__ w1,
                            const float* __restrict__ w2)
{
    int blk = blockIdx.x;
    if (blk < MTOT) {
        int row = blk;
        int bb  = row >> 12;
        int tok = g_sel[row];
        const float4* src = (const float4*)(x + (size_t)(bb*Tt + tok) * Dd);
        float4*       dst = (float4*)(g_xg + (size_t)row * Dd);
        float4 v = src[threadIdx.x];
        v.x = rnd_tf32(v.x); v.y = rnd_tf32(v.y);
        v.z = rnd_tf32(v.z); v.w = rnd_tf32(v.w);
        dst[threadIdx.x] = v;
        return;
    }
    __shared__ float tbuf[32][33];
    int tile = blk - MTOT;
    const float* in; float* outp; int R, C, bx, by;
    if (tile < W1_TILES) {               // w1 [Dd][Ff] -> g_w1t [Ff][Dd]
        in = w1; R = Dd; C = Ff;
        bx = (tile % (Ff/32)) * 32; by = (tile / (Ff/32)) * 32;
        outp = g_w1t;
    } else {                             // w2 [Ff][Dd] -> g_w2t [Dd][Ff]
        tile -= W1_TILES;
        in = w2; R = Ff; C = Dd;
        bx = (tile % (Dd/32)) * 32; by = (tile / (Dd/32)) * 32;
        outp = g_w2t;
    }
    int xt = threadIdx.x & 31, yt = threadIdx.x >> 5;
    #pragma unroll
    for (int j = 0; j < 32; j += 8)
        tbuf[yt + j][xt] = in[(size_t)(by + yt + j) * C + bx + xt];
    __syncthreads();
    #pragma unroll
    for (int j = 0; j < 32; j += 8)
        outp[(size_t)(bx + yt + j) * R + by + xt] = rnd_tf32(tbuf[xt][yt + j]);
}

// ---------------------------------------------------------------------------
// tf32 mma.sync GEMM — R11 configuration (empirical optimum of this family):
// 128x128x32 tiles, 4 warps/CTA, 64x64 warptiles, 2-stage cp.async,
// 3 CTAs/SM, dual barrier per iter, all fragments via ldmatrix.x4, inline
// B ldsm. kt loop unrolled x2 so (kt&1) buffer offsets are compile-time.
// PH1: g_h = tf32(gelu(g_xg @ w1t^T + b1))    (KD=1024, ND=4096)
// PH2: scatter(out) = g_h @ w2t^T + b2        (KD=4096, ND=1024)
// ---------------------------------------------------------------------------
#define BM  128
#define BN  128
#define BK  32
#define AST 36
#define STG_FLOATS (BM*AST + BN*AST)          // 9216 floats / stage
#define STG_BYTES  (STG_FLOATS * 4)           // 36864 B
#define SMEM_BYTES (2 * STG_BYTES)            // 73728 B -> 3 CTAs/SM

template<int KD, int ND, bool PH1>
__global__ void __launch_bounds__(128, 3)
gemm_tf32(const float* __restrict__ A,      // pre-rounded, row-major [rows][KD]
          const float* __restrict__ Bt,     // pre-rounded W^T, row-major [ND][KD]
          const float* __restrict__ bias,
          float* __restrict__ C)
{
    extern __shared__ float sm[];
    const uint32_t smb = smem_u32(sm);
    const int tid  = threadIdx.x;
    const int warp = tid >> 5, lane = tid & 31;
    const int m0   = blockIdx.y * BM;
    const int n0   = blockIdx.x * BN;

    const float* abase = A  + (size_t)(m0 + (tid >> 3)) * KD + ((tid & 7) << 2);
    const float* bbase = Bt + (size_t)(n0 + (tid >> 3)) * KD + ((tid & 7) << 2);
    const uint32_t adst = smb + (uint32_t)((tid >> 3)*AST + ((tid & 7) << 2)) * 4;
    const uint32_t bdst = adst + (uint32_t)(BM*AST) * 4;

    const int wm = (warp >> 1) * 64, wn = (warp & 1) * 64;

    const int arow_off = (lane & 7) + ((lane >> 3) & 1) * 8;
    const int acol_off = (lane >> 4) * 4;
    uint32_t afrag[4];
    #pragma unroll
    for (int mt = 0; mt < 4; mt++)
        afrag[mt] = smb + (uint32_t)((wm + mt*16 + arow_off)*AST + acol_off) * 4;

    const int brow_off = (lane & 7) + ((lane >> 4) & 1) * 8;
    const int bcol_off = ((lane >> 3) & 1) * 4;
    uint32_t bfrag[4];
    #pragma unroll
    for (int p = 0; p < 4; p++)
        bfrag[p] = smb + (uint32_t)(BM*AST + (wn + p*16 + brow_off)*AST + bcol_off) * 4;

    float acc[4][8][4];
    #pragma unroll
    for (int i = 0; i < 4; i++)
        #pragma unroll
        for (int jn = 0; jn < 8; jn++)
            #pragma unroll
            for (int q = 0; q < 4; q++) acc[i][jn][q] = 0.f;

    const int nk = KD / BK;

    #pragma unroll
    for (int p = 0; p < 2; p++) {
        uint32_t bo = (uint32_t)p * STG_BYTES;
        #pragma unroll
        for (int j = 0; j < 8; j++)
            cp16(adst + bo + (uint32_t)(j*16*AST)*4, abase + p*BK + (size_t)j*16*KD);
        #pragma unroll
        for (int j = 0; j < 8; j++)
            cp16(bdst + bo + (uint32_t)(j*16*AST)*4, bbase + p*BK + (size_t)j*16*KD);
        CP_COMMIT();
    }

    #pragma unroll 2
    for (int kt = 0; kt < nk; kt++) {
        CP_WAIT1();
        __syncthreads();

        const uint32_t bufo = (uint32_t)(kt & 1) * STG_BYTES;

        #pragma unroll
        for (int k8 = 0; k8 < BK; k8 += 8) {
            unsigned af[4][4];
            #pragma unroll
            for (int mt = 0; mt < 4; mt++)
                ldsm4(af[mt], afrag[mt] + bufo + (uint32_t)k8 * 4);

            #pragma unroll
            for (int p = 0; p < 4; p++) {          // p covers n-tiles 2p, 2p+1
                unsigned bb[4];
                ldsm4(bb, bfrag[p] + bufo + (uint32_t)k8 * 4);
                #pragma unroll
                for (int mt = 0; mt < 4; mt++)
                    mma8(acc[mt][2*p + 0], af[mt], bb + 0);
                #pragma unroll
                for (int mt = 0; mt < 4; mt++)
                    mma8(acc[mt][2*p + 1], af[mt], bb + 2);
            }
        }

        __syncthreads();   // all warps done reading buf kt&1 before refill

        if (kt + 2 < nk) {
            uint32_t bo = (uint32_t)(kt & 1) * STG_BYTES;
            int kofs = (kt + 2) * BK;
            #pragma unroll
            for (int j = 0; j < 8; j++)
                cp16(adst + bo + (uint32_t)(j*16*AST)*4, abase + kofs + (size_t)j*16*KD);
            #pragma unroll
            for (int j = 0; j < 8; j++)
                cp16(bdst + bo + (uint32_t)(j*16*AST)*4, bbase + kofs + (size_t)j*16*KD);
        }
        CP_COMMIT();
    }

    // epilogue: bias (+gelu+round for PH1); PH1 linear store, PH2 scatter
    #pragma unroll
    for (int mt = 0; mt < 4; mt++) {
        #pragma unroll
        for (int half = 0; half < 2; half++) {
            int row = m0 + wm + mt*16 + (lane >> 2) + half*8;
            size_t ob;
            if (PH1) ob = (size_t)row * ND;
            else { int bb2 = row >> 12; ob = ((size_t)(bb2*Tt + g_sel[row])) * (size_t)ND; }
            #pragma unroll
            for (int nt = 0; nt < 8; nt++) {
                int col = n0 + wn + nt*8 + (lane & 3)*2;
                float v0 = acc[mt][nt][half*2 + 0] + bias[col];
                float v1 = acc[mt][nt][half*2 + 1] + bias[col + 1];
                if (PH1) { v0 = rnd_tf32(gelu_t(v0)); v1 = rnd_tf32(gelu_t(v1)); }
                *(float2*)(C + ob + col) = make_float2(v0, v1);
            }
        }
    }
}

// ---------------------------------------------------------------------------
extern "C" void kernel_launch(void* const* d_in, const int* in_sizes, int n_in,
                              void* d_out, int out_size)
{
    const float* x  = (const float*)d_in[0];
    const float* wr = (const float*)d_in[1];
    const float* w1 = (const float*)d_in[2];
    const float* b1 = (const float*)d_in[3];
    const float* w2 = (const float*)d_in[4];
    const float* b2 = (const float*)d_in[5];
    float* out = (float*)d_out;

    float* xg;  cudaGetSymbolAddress((void**)&xg,  g_xg);
    float* h;   cudaGetSymbolAddress((void**)&h,   g_h);
    float* w1t; cudaGetSymbolAddress((void**)&w1t, g_w1t);
    float* w2t; cudaGetSymbolAddress((void**)&w2t, g_w2t);

    // order: scores+copy(1), select(2), prep(3), gemm1(4), gemm2(5)
    scores_copy_kernel<<<(Bb*Tt)/8, 256>>>(x, wr, out);
    select_kernel<<<Bb, 1024>>>();
    prep_kernel<<<MTOT + W1_TILES + W2_TILES, 256>>>(x, w1, w2);

    cudaFuncSetAttribute(gemm_tf32<Dd, Ff, true>,
                         cudaFuncAttributeMaxDynamicSharedMemorySize, SMEM_BYTES);
    cudaFuncSetAttribute(gemm_tf32<Ff, Dd, false>,
                         cudaFuncAttributeMaxDynamicSharedMemorySize, SMEM_BYTES);
    dim3 g1(Ff/BN, MTOT/BM);   // 32 x 128
    dim3 g2(Dd/BN, MTOT/BM);   //  8 x 128
    gemm_tf32<Dd, Ff, true ><<<g1, 128, SMEM_BYTES>>>(xg, w1t, b1, h);
    gemm_tf32<Ff, Dd, false><<<g2, 128, SMEM_BYTES>>>(h,  w2t, b2, out);
}

// round 16
// speedup vs baseline: 1.7603x; 1.5635x over previous
#include <cuda_runtime.h>
#include <cuda_fp16.h>
#include <cstdint>
#include <math.h>

#define Bb   4
#define Tt   8192
#define Dd   1024
#define Ff   4096
#define CAP  4096
#define MTOT (Bb*CAP)   // 16384 selected tokens

// ---------------- scratch (device globals: allocation-free rule) ------------
__device__ float  g_scores[Bb*Tt];
__device__ int    g_sel[MTOT];
__device__ __align__(16) __half g_xh [(size_t)MTOT * (size_t)Dd];  // gathered x, fp16 (32MB)
__device__ __align__(16) __half g_h  [(size_t)MTOT * (size_t)Ff];  // hidden, fp16 (128MB)
__device__ __align__(16) __half g_w1t[(size_t)Ff * (size_t)Dd];    // w1^T fp16 [F][D] (8MB)
__device__ __align__(16) __half g_w2t[(size_t)Dd * (size_t)Ff];    // w2^T fp16 [D][F] (8MB)

// ---------------------------------------------------------------------------
__device__ __forceinline__ uint32_t smem_u32(const void* p) {
    uint32_t a;
    asm("{ .reg .u64 t; cvta.to.shared.u64 t, %1; cvt.u32.u64 %0, t; }" : "=r"(a) : "l"(p));
    return a;
}
__device__ __forceinline__ void cp16(uint32_t dst, const void* src) {
    asm volatile("cp.async.cg.shared.global [%0], [%1], 16;" :: "r"(dst), "l"(src) : "memory");
}
#define CP_COMMIT() asm volatile("cp.async.commit_group;" ::: "memory")
#define CP_WAIT1()  asm volatile("cp.async.wait_group 1;" ::: "memory")

__device__ __forceinline__ void ldsm4(unsigned* r, uint32_t addr) {
    asm volatile("ldmatrix.sync.aligned.m8n8.x4.shared.b16 {%0,%1,%2,%3}, [%4];"
                 : "=r"(r[0]), "=r"(r[1]), "=r"(r[2]), "=r"(r[3]) : "r"(addr));
}
// fp16 mma: m16n8k16, row.col, fp32 accumulate
__device__ __forceinline__ void mma16(float* d, const unsigned* a, const unsigned* b) {
    asm volatile(
        "mma.sync.aligned.m16n8k16.row.col.f32.f16.f16.f32 "
        "{%0,%1,%2,%3},{%4,%5,%6,%7},{%8,%9},{%0,%1,%2,%3};\n"
        : "+f"(d[0]), "+f"(d[1]), "+f"(d[2]), "+f"(d[3])
        : "r"(a[0]), "r"(a[1]), "r"(a[2]), "r"(a[3]), "r"(b[0]), "r"(b[1]));
}
__device__ __forceinline__ float gelu_t(float x) {   // jax gelu approximate=True
    float u = 0.7978845608028654f * (x + 0.044715f * x * x * x);
    return 0.5f * x * (1.0f + tanhf(u));
}

// ---------------------------------------------------------------------------
// Kernel 1: router scores (one warp per token) fused with passthrough copy
// ---------------------------------------------------------------------------
__global__ void scores_copy_kernel(const float* __restrict__ x,
                                   const float* __restrict__ wr,
                                   float* __restrict__ out)
{
    int gw   = (blockIdx.x * blockDim.x + threadIdx.x) >> 5;
    int lane = threadIdx.x & 31;
    const float* xr   = x   + (size_t)gw * Dd;
    float*       orow = out + (size_t)gw * Dd;
    float s = 0.f;
    #pragma unroll
    for (int i = 0; i < Dd; i += 128) {
        float4 a = *(const float4*)(xr + i + lane*4);
        float4 w = *(const float4*)(wr + i + lane*4);
        *(float4*)(orow + i + lane*4) = a;          // passthrough copy
        s += a.x*w.x; s += a.y*w.y; s += a.z*w.z; s += a.w*w.w;
    }
    #pragma unroll
    for (int o = 16; o; o >>= 1) s += __shfl_xor_sync(0xffffffffu, s, o);
    if (lane == 0) g_scores[gw] = s;
}

// ---------------------------------------------------------------------------
// Kernel 2: per-row top-CAP radix select (ties lowest-index-first)
// ---------------------------------------------------------------------------
__global__ void select_kernel()
{
    __shared__ unsigned keys[Tt];
    __shared__ int      hist[256];
    __shared__ int      wsum[32];
    __shared__ unsigned s_prefix;
    __shared__ int      s_k, s_cnt, s_pos;

    const int b = blockIdx.x;
    const int t = threadIdx.x;
    const int lane = t & 31, wid = t >> 5;

    for (int i = t; i < Tt; i += 1024) {
        unsigned u = __float_as_uint(g_scores[b*Tt + i]);
        u = (u & 0x80000000u) ? ~u : (u | 0x80000000u);
        keys[i] = u;
    }
    if (t == 0) { s_prefix = 0u; s_k = CAP; }
    __syncthreads();

    for (int shift = 24; shift >= 0; shift -= 8) {
        if (t < 256) hist[t] = 0;
        __syncthreads();
        unsigned hi  = (shift == 24) ? 0u : (0xFFFFFFFFu << (shift + 8));
        unsigned pfx = s_prefix;
        for (int i = t; i < Tt; i += 1024) {
            unsigned k = keys[i];
            if ((k & hi) == pfx) atomicAdd(&hist[(k >> shift) & 255], 1);
        }
        __syncthreads();
        if (t == 0) {
            int k = s_k, bin;
            for (bin = 255; bin > 0; bin--) {
                int c = hist[bin];
                if (c >= k) break;
                k -= c;
            }
            s_prefix |= ((unsigned)bin) << shift;
            s_k = k;
        }
        __syncthreads();
    }
    const unsigned thresh = s_prefix;

    if (t == 0) { s_cnt = 0; s_pos = 0; }
    __syncthreads();
    int loc = 0;
    for (int i = t; i < Tt; i += 1024) if (keys[i] > thresh) loc++;
    atomicAdd(&s_cnt, loc);
    __syncthreads();
    const int greater = s_cnt;
    const int need    = CAP - greater;

    for (int i = t; i < Tt; i += 1024)
        if (keys[i] > thresh) { int p = atomicAdd(&s_pos, 1); g_sel[b*CAP + p] = i; }

    int cnt = 0;
    #pragma unroll
    for (int j = 0; j < 8; j++) if (keys[t*8 + j] == thresh) cnt++;
    int v = cnt;
    #pragma unroll
    for (int o = 1; o < 32; o <<= 1) {
        int u = __shfl_up_sync(0xffffffffu, v, o);
        if (lane >= o) v += u;
    }
    if (lane == 31) wsum[wid] = v;
    __syncthreads();
    if (wid == 0) {
        int s = wsum[lane];
        #pragma unroll
        for (int o = 1; o < 32; o <<= 1) {
            int u = __shfl_up_sync(0xffffffffu, s, o);
            if (lane >= o) s += u;
        }
        wsum[lane] = s;
    }
    __syncthreads();
    int base = (wid > 0) ? wsum[wid - 1] : 0;
    int r = base + v - cnt;
    #pragma unroll
    for (int j = 0; j < 8; j++) {
        int i = t*8 + j;
        if (keys[i] == thresh) {
            if (r < need) g_sel[b*CAP + greater + r] = i;
            r++;
        }
    }
}

// ---------------------------------------------------------------------------
// Kernel 3: FUSED prep: gather selected rows -> fp16 AND both weight
// transposes -> fp16. blocks [0,MTOT): gather; rest: 32x32 transpose tiles.
// ---------------------------------------------------------------------------
#define W1_TILES ((Dd/32)*(Ff/32))   // 4096
#define W2_TILES ((Ff/32)*(Dd/32))   // 4096

__global__ void prep_kernel(const float* __restrict__ x,
                            const float* __restrict__ w1,
                            const float* __restrict__ w2)
{
    int blk = blockIdx.x;
    if (blk < MTOT) {
        int row = blk;
        int bb  = row >> 12;
        int tok = g_sel[row];
        const float4* src = (const float4*)(x + (size_t)(bb*Tt + tok) * Dd);
        float4 v = src[threadIdx.x];
        __half2* dst = (__half2*)(g_xh + (size_t)row * Dd);
        dst[threadIdx.x*2 + 0] = __floats2half2_rn(v.x, v.y);
        dst[threadIdx.x*2 + 1] = __floats2half2_rn(v.z, v.w);
        return;
    }
    __shared__ float tbuf[32][33];
    int tile = blk - MTOT;
    const float* in; __half* outp; int R, C, bx, by;
    if (tile < W1_TILES) {               // w1 [Dd][Ff] -> g_w1t [Ff][Dd]
        in = w1; R = Dd; C = Ff;
        bx = (tile % (Ff/32)) * 32; by = (tile / (Ff/32)) * 32;
        outp = g_w1t;
    } else {                             // w2 [Ff][Dd] -> g_w2t [Dd][Ff]
        tile -= W1_TILES;
        in = w2; R = Ff; C = Dd;
        bx = (tile % (Dd/32)) * 32; by = (tile / (Dd/32)) * 32;
        outp = g_w2t;
    }
    int xt = threadIdx.x & 31, yt = threadIdx.x >> 5;
    #pragma unroll
    for (int j = 0; j < 32; j += 8)
        tbuf[yt + j][xt] = in[(size_t)(by + yt + j) * C + bx + xt];
    __syncthreads();
    #pragma unroll
    for (int j = 0; j < 32; j += 8)
        outp[(size_t)(bx + yt + j) * R + by + xt] = __float2half_rn(tbuf[xt][yt + j]);
}

// ---------------------------------------------------------------------------
// fp16 mma.sync GEMM (m16n8k16), 128x128x32 tiles, 4 warps/CTA, 64x64
// warptiles, 2-stage cp.async, dual barrier (R11 skeleton), 3 CTAs/SM.
// A m-major, B n-major fp16 tiles, stride 40 halves (80B row): LDSM phase
// banks 20r+4κ mod 32 -> all 32 banks once, conflict-free. Both fragment
// sets via ldmatrix.x4.b16 non-trans (n-major B gives the col-B fragment).
// PH1: g_h = fp16(gelu(g_xh @ w1t^T + b1))    (KD=1024, ND=4096)
// PH2: scatter(out) = g_h @ w2t^T + b2        (KD=4096, ND=1024)
// ---------------------------------------------------------------------------
#define BM  128
#define BN  128
#define BK  32
#define AH  40                                 // stride in halves (80 B)
#define STG_HALVES ((BM + BN) * AH)            // 10240 halves / stage
#define STG_BYTES  (STG_HALVES * 2)            // 20480 B
#define SMEM_BYTES (2 * STG_BYTES)             // 40960 B -> 3 CTAs/SM (regs cap)

template<int KD, int ND, bool PH1>
__global__ void __launch_bounds__(128, 3)
gemm_fp16(const __half* __restrict__ A,      // [rows][KD] fp16
          const __half* __restrict__ Bt,     // W^T [ND][KD] fp16
          const float* __restrict__ bias,
          float* __restrict__ Out)           // PH2 scatter target (PH1: unused)
{
    extern __shared__ char smc[];
    const uint32_t smb = smem_u32(smc);
    const int tid  = threadIdx.x;
    const int warp = tid >> 5, lane = tid & 31;
    const int m0   = blockIdx.y * BM;
    const int n0   = blockIdx.x * BN;

    // staging: per stage A = 128 rows x 64B (4 cp16/thread), B same
    // thread -> row (tid>>2)+32j, half-col (tid&3)*8
    const __half* abase = A  + (size_t)(m0 + (tid >> 2)) * KD + ((tid & 3) << 3);
    const __half* bbase = Bt + (size_t)(n0 + (tid >> 2)) * KD + ((tid & 3) << 3);
    const uint32_t adst = smb + (uint32_t)((tid >> 2)*AH + ((tid & 3) << 3)) * 2;
    const uint32_t bdst = adst + (uint32_t)(BM*AH) * 2;

    const int wm = (warp >> 1) * 64, wn = (warp & 1) * 64;

    // A fragment lane map: m0=(r0-7,k0-7) m1=(r8-15,k0-7) m2=(r0-7,k8-15) m3=(r8-15,k8-15)
    const int arow = (lane & 7) + ((lane >> 3) & 1) * 8;
    const int akh  = (lane >> 4) * 8;                  // halves
    uint32_t afrag[4];
    #pragma unroll
    for (int mt = 0; mt < 4; mt++)
        afrag[mt] = smb + (uint32_t)((wm + mt*16 + arow)*AH + akh) * 2;

    // B fragment lane map (covers 2 n-tiles per ldsm4):
    // m0=(n0-7,k0-7) m1=(n0-7,k8-15) m2=(n8-15,k0-7) m3=(n8-15,k8-15)
    const int brow = (lane & 7) + ((lane >> 4) & 1) * 8;
    const int bkh  = ((lane >> 3) & 1) * 8;
    uint32_t bfrag[4];
    #pragma unroll
    for (int p = 0; p < 4; p++)
        bfrag[p] = smb + (uint32_t)(BM*AH + (wn + p*16 + brow)*AH + bkh) * 2;

    float acc[4][8][4];
    #pragma unroll
    for (int i = 0; i < 4; i++)
        #pragma unroll
        for (int jn = 0; jn < 8; jn++)
            #pragma unroll
            for (int q = 0; q < 4; q++) acc[i][jn][q] = 0.f;

    const int nk = KD / BK;

    // prologue: issue tiles 0, 1
    #pragma unroll
    for (int p = 0; p < 2; p++) {
        uint32_t bo = (uint32_t)p * STG_BYTES;
        #pragma unroll
        for (int j = 0; j < 4; j++)
            cp16(adst + bo + (uint32_t)(j*32*AH)*2, abase + p*BK + (size_t)j*32*KD);
        #pragma unroll
        for (int j = 0; j < 4; j++)
            cp16(bdst + bo + (uint32_t)(j*32*AH)*2, bbase + p*BK + (size_t)j*32*KD);
        CP_COMMIT();
    }

    for (int kt = 0; kt < nk; kt++) {
        CP_WAIT1();
        __syncthreads();

        const uint32_t bufo = (uint32_t)(kt & 1) * STG_BYTES;

        #pragma unroll
        for (int s = 0; s < 2; s++) {              // two k16 steps per BK=32
            const uint32_t so = bufo + (uint32_t)s * 32;   // 16 halves = 32 B
            unsigned af[4][4];
            #pragma unroll
            for (int mt = 0; mt < 4; mt++)
                ldsm4(af[mt], afrag[mt] + so);

            #pragma unroll
            for (int p = 0; p < 4; p++) {          // p covers n-tiles 2p, 2p+1
                unsigned bb[4];
                ldsm4(bb, bfrag[p] + so);
                #pragma unroll
                for (int mt = 0; mt < 4; mt++)
                    mma16(acc[mt][2*p + 0], af[mt], bb + 0);
                #pragma unroll
                for (int mt = 0; mt < 4; mt++)
                    mma16(acc[mt][2*p + 1], af[mt], bb + 2);
            }
        }

        __syncthreads();   // all warps done reading buf kt&1 before refill

        if (kt + 2 < nk) {
            uint32_t bo = (uint32_t)(kt & 1) * STG_BYTES;
            int kofs = (kt + 2) * BK;
            #pragma unroll
            for (int j = 0; j < 4; j++)
                cp16(adst + bo + (uint32_t)(j*32*AH)*2, abase + kofs + (size_t)j*32*KD);
            #pragma unroll
            for (int j = 0; j < 4; j++)
                cp16(bdst + bo + (uint32_t)(j*32*AH)*2, bbase + kofs + (size_t)j*32*KD);
        }
        CP_COMMIT();
    }

    // epilogue: bias (+gelu for PH1); PH1 -> g_h (fp16), PH2 -> scatter fp32
    #pragma unroll
    for (int mt = 0; mt < 4; mt++) {
        #pragma unroll
        for (int half = 0; half < 2; half++) {
            int row = m0 + wm + mt*16 + (lane >> 2) + half*8;
            #pragma unroll
            for (int nt = 0; nt < 8; nt++) {
                int col = n0 + wn + nt*8 + (lane & 3)*2;
                float v0 = acc[mt][nt][half*2 + 0] + bias[col];
                float v1 = acc[mt][nt][half*2 + 1] + bias[col + 1];
                if (PH1) {
                    v0 = gelu_t(v0); v1 = gelu_t(v1);
                    __half2 hv = __floats2half2_rn(v0, v1);
                    *(__half2*)(g_h + (size_t)row * ND + col) = hv;
                } else {
                    int bb2 = row >> 12;
                    size_t ob = ((size_t)(bb2*Tt + g_sel[row])) * (size_t)ND;
                    *(float2*)(Out + ob + col) = make_float2(v0, v1);
                }
            }
        }
    }
}

// ---------------------------------------------------------------------------
extern "C" void kernel_launch(void* const* d_in, const int* in_sizes, int n_in,
                              void* d_out, int out_size)
{
    const float* x  = (const float*)d_in[0];
    const float* wr = (const float*)d_in[1];
    const float* w1 = (const float*)d_in[2];
    const float* b1 = (const float*)d_in[3];
    const float* w2 = (const float*)d_in[4];
    const float* b2 = (const float*)d_in[5];
    float* out = (float*)d_out;

    __half* xh;  cudaGetSymbolAddress((void**)&xh,  g_xh);
    __half* h;   cudaGetSymbolAddress((void**)&h,   g_h);
    __half* w1t; cudaGetSymbolAddress((void**)&w1t, g_w1t);
    __half* w2t; cudaGetSymbolAddress((void**)&w2t, g_w2t);

    // order: scores+copy(1), select(2), prep(3), gemm1(4), gemm2(5)
    scores_copy_kernel<<<(Bb*Tt)/8, 256>>>(x, wr, out);
    select_kernel<<<Bb, 1024>>>();
    prep_kernel<<<MTOT + W1_TILES + W2_TILES, 256>>>(x, w1, w2);

    cudaFuncSetAttribute(gemm_fp16<Dd, Ff, true>,
                         cudaFuncAttributeMaxDynamicSharedMemorySize, SMEM_BYTES);
    cudaFuncSetAttribute(gemm_fp16<Ff, Dd, false>,
                         cudaFuncAttributeMaxDynamicSharedMemorySize, SMEM_BYTES);
    dim3 g1(Ff/BN, MTOT/BM);   // 32 x 128
    dim3 g2(Dd/BN, MTOT/BM);   //  8 x 128
    gemm_fp16<Dd, Ff, true ><<<g1, 128, SMEM_BYTES>>>(xh, w1t, b1, nullptr);
    gemm_fp16<Ff, Dd, false><<<g2, 128, SMEM_BYTES>>>(h,  w2t, b2, out);
}

// round 17
// speedup vs baseline: 2.0313x; 1.1540x over previous
#include <cuda_runtime.h>
#include <cuda_fp16.h>
#include <cstdint>
#include <math.h>

#define Bb   4
#define Tt   8192
#define Dd   1024
#define Ff   4096
#define CAP  4096
#define MTOT (Bb*CAP)   // 16384 selected tokens

// ---------------- scratch (device globals: allocation-free rule) ------------
__device__ float  g_scores[Bb*Tt];
__device__ int    g_sel[MTOT];
__device__ __align__(16) __half g_xh [(size_t)MTOT * (size_t)Dd];  // gathered x, fp16 (32MB)
__device__ __align__(16) __half g_h  [(size_t)MTOT * (size_t)Ff];  // hidden, fp16 (128MB)
__device__ __align__(16) __half g_w1t[(size_t)Ff * (size_t)Dd];    // w1^T fp16 [F][D] (8MB)
__device__ __align__(16) __half g_w2t[(size_t)Dd * (size_t)Ff];    // w2^T fp16 [D][F] (8MB)

// ---------------------------------------------------------------------------
__device__ __forceinline__ uint32_t smem_u32(const void* p) {
    uint32_t a;
    asm("{ .reg .u64 t; cvta.to.shared.u64 t, %1; cvt.u32.u64 %0, t; }" : "=r"(a) : "l"(p));
    return a;
}
__device__ __forceinline__ void cp16(uint32_t dst, const void* src) {
    asm volatile("cp.async.cg.shared.global [%0], [%1], 16;" :: "r"(dst), "l"(src) : "memory");
}
#define CP_COMMIT() asm volatile("cp.async.commit_group;" ::: "memory")
#define CP_WAIT1()  asm volatile("cp.async.wait_group 1;" ::: "memory")

__device__ __forceinline__ void ldsm4(unsigned* r, uint32_t addr) {
    asm volatile("ldmatrix.sync.aligned.m8n8.x4.shared.b16 {%0,%1,%2,%3}, [%4];"
                 : "=r"(r[0]), "=r"(r[1]), "=r"(r[2]), "=r"(r[3]) : "r"(addr));
}
// fp16 mma: m16n8k16, row.col, fp32 accumulate
__device__ __forceinline__ void mma16(float* d, const unsigned* a, const unsigned* b) {
    asm volatile(
        "mma.sync.aligned.m16n8k16.row.col.f32.f16.f16.f32 "
        "{%0,%1,%2,%3},{%4,%5,%6,%7},{%8,%9},{%0,%1,%2,%3};\n"
        : "+f"(d[0]), "+f"(d[1]), "+f"(d[2]), "+f"(d[3])
        : "r"(a[0]), "r"(a[1]), "r"(a[2]), "r"(a[3]), "r"(b[0]), "r"(b[1]));
}
__device__ __forceinline__ float gelu_t(float x) {   // jax gelu approximate=True
    float u = 0.7978845608028654f * (x + 0.044715f * x * x * x);
    return 0.5f * x * (1.0f + tanhf(u));
}

// ---------------------------------------------------------------------------
// Kernel 1: router scores (one warp per token) fused with passthrough copy
// ---------------------------------------------------------------------------
__global__ void scores_copy_kernel(const float* __restrict__ x,
                                   const float* __restrict__ wr,
                                   float* __restrict__ out)
{
    int gw   = (blockIdx.x * blockDim.x + threadIdx.x) >> 5;
    int lane = threadIdx.x & 31;
    const float* xr   = x   + (size_t)gw * Dd;
    float*       orow = out + (size_t)gw * Dd;
    float s = 0.f;
    #pragma unroll
    for (int i = 0; i < Dd; i += 128) {
        float4 a = *(const float4*)(xr + i + lane*4);
        float4 w = *(const float4*)(wr + i + lane*4);
        *(float4*)(orow + i + lane*4) = a;          // passthrough copy
        s += a.x*w.x; s += a.y*w.y; s += a.z*w.z; s += a.w*w.w;
    }
    #pragma unroll
    for (int o = 16; o; o >>= 1) s += __shfl_xor_sync(0xffffffffu, s, o);
    if (lane == 0) g_scores[gw] = s;
}

// ---------------------------------------------------------------------------
// Kernel 2: per-row top-CAP radix select (ties lowest-index-first)
// ---------------------------------------------------------------------------
__global__ void select_kernel()
{
    __shared__ unsigned keys[Tt];
    __shared__ int      hist[256];
    __shared__ int      wsum[32];
    __shared__ unsigned s_prefix;
    __shared__ int      s_k, s_cnt, s_pos;

    const int b = blockIdx.x;
    const int t = threadIdx.x;
    const int lane = t & 31, wid = t >> 5;

    for (int i = t; i < Tt; i += 1024) {
        unsigned u = __float_as_uint(g_scores[b*Tt + i]);
        u = (u & 0x80000000u) ? ~u : (u | 0x80000000u);
        keys[i] = u;
    }
    if (t == 0) { s_prefix = 0u; s_k = CAP; }
    __syncthreads();

    for (int shift = 24; shift >= 0; shift -= 8) {
        if (t < 256) hist[t] = 0;
        __syncthreads();
        unsigned hi  = (shift == 24) ? 0u : (0xFFFFFFFFu << (shift + 8));
        unsigned pfx = s_prefix;
        for (int i = t; i < Tt; i += 1024) {
            unsigned k = keys[i];
            if ((k & hi) == pfx) atomicAdd(&hist[(k >> shift) & 255], 1);
        }
        __syncthreads();
        if (t == 0) {
            int k = s_k, bin;
            for (bin = 255; bin > 0; bin--) {
                int c = hist[bin];
                if (c >= k) break;
                k -= c;
            }
            s_prefix |= ((unsigned)bin) << shift;
            s_k = k;
        }
        __syncthreads();
    }
    const unsigned thresh = s_prefix;

    if (t == 0) { s_cnt = 0; s_pos = 0; }
    __syncthreads();
    int loc = 0;
    for (int i = t; i < Tt; i += 1024) if (keys[i] > thresh) loc++;
    atomicAdd(&s_cnt, loc);
    __syncthreads();
    const int greater = s_cnt;
    const int need    = CAP - greater;

    for (int i = t; i < Tt; i += 1024)
        if (keys[i] > thresh) { int p = atomicAdd(&s_pos, 1); g_sel[b*CAP + p] = i; }

    int cnt = 0;
    #pragma unroll
    for (int j = 0; j < 8; j++) if (keys[t*8 + j] == thresh) cnt++;
    int v = cnt;
    #pragma unroll
    for (int o = 1; o < 32; o <<= 1) {
        int u = __shfl_up_sync(0xffffffffu, v, o);
        if (lane >= o) v += u;
    }
    if (lane == 31) wsum[wid] = v;
    __syncthreads();
    if (wid == 0) {
        int s = wsum[lane];
        #pragma unroll
        for (int o = 1; o < 32; o <<= 1) {
            int u = __shfl_up_sync(0xffffffffu, s, o);
            if (lane >= o) s += u;
        }
        wsum[lane] = s;
    }
    __syncthreads();
    int base = (wid > 0) ? wsum[wid - 1] : 0;
    int r = base + v - cnt;
    #pragma unroll
    for (int j = 0; j < 8; j++) {
        int i = t*8 + j;
        if (keys[i] == thresh) {
            if (r < need) g_sel[b*CAP + greater + r] = i;
            r++;
        }
    }
}

// ---------------------------------------------------------------------------
// Kernel 3: FUSED prep: gather selected rows -> fp16 AND both weight
// transposes -> fp16.
// ---------------------------------------------------------------------------
#define W1_TILES ((Dd/32)*(Ff/32))   // 4096
#define W2_TILES ((Ff/32)*(Dd/32))   // 4096

__global__ void prep_kernel(const float* __restrict__ x,
                            const float* __restrict__ w1,
                            const float* __restrict__ w2)
{
    int blk = blockIdx.x;
    if (blk < MTOT) {
        int row = blk;
        int bb  = row >> 12;
        int tok = g_sel[row];
        const float4* src = (const float4*)(x + (size_t)(bb*Tt + tok) * Dd);
        float4 v = src[threadIdx.x];
        __half2* dst = (__half2*)(g_xh + (size_t)row * Dd);
        dst[threadIdx.x*2 + 0] = __floats2half2_rn(v.x, v.y);
        dst[threadIdx.x*2 + 1] = __floats2half2_rn(v.z, v.w);
        return;
    }
    __shared__ float tbuf[32][33];
    int tile = blk - MTOT;
    const float* in; __half* outp; int R, C, bx, by;
    if (tile < W1_TILES) {               // w1 [Dd][Ff] -> g_w1t [Ff][Dd]
        in = w1; R = Dd; C = Ff;
        bx = (tile % (Ff/32)) * 32; by = (tile / (Ff/32)) * 32;
        outp = g_w1t;
    } else {                             // w2 [Ff][Dd] -> g_w2t [Dd][Ff]
        tile -= W1_TILES;
        in = w2; R = Ff; C = Dd;
        bx = (tile % (Dd/32)) * 32; by = (tile / (Dd/32)) * 32;
        outp = g_w2t;
    }
    int xt = threadIdx.x & 31, yt = threadIdx.x >> 5;
    #pragma unroll
    for (int j = 0; j < 32; j += 8)
        tbuf[yt + j][xt] = in[(size_t)(by + yt + j) * C + bx + xt];
    __syncthreads();
    #pragma unroll
    for (int j = 0; j < 32; j += 8)
        outp[(size_t)(bx + yt + j) * R + by + xt] = __float2half_rn(tbuf[xt][yt + j]);
}

// ---------------------------------------------------------------------------
// fp16 mma.sync GEMM (m16n8k16), 128x128 tiles, BK=64 (half the stage
// boundaries of R15: per-kt overhead amortized over 128 HMMA), 4 warps/CTA,
// 64x64 warptiles, 2-stage cp.async, dual barrier, 3 CTAs/SM (221KB smem).
// Stride 72 halves (144B row): LDSM 8-row phase steps 4 banks/row -> all 32
// banks once, conflict-free.
// PH1: g_h = fp16(gelu(g_xh @ w1t^T + b1))    (KD=1024, ND=4096)
// PH2: scatter(out) = g_h @ w2t^T + b2        (KD=4096, ND=1024)
// ---------------------------------------------------------------------------
#define BM  128
#define BN  128
#define BK  64
#define AH  72                                 // stride in halves (144 B)
#define STG_HALVES ((BM + BN) * AH)            // 18432 halves / stage
#define STG_BYTES  (STG_HALVES * 2)            // 36864 B
#define SMEM_BYTES (2 * STG_BYTES)             // 73728 B -> 3 CTAs/SM

template<int KD, int ND, bool PH1>
__global__ void __launch_bounds__(128, 3)
gemm_fp16(const __half* __restrict__ A,      // [rows][KD] fp16
          const __half* __restrict__ Bt,     // W^T [ND][KD] fp16
          const float* __restrict__ bias,
          float* __restrict__ Out)           // PH2 scatter target (PH1: unused)
{
    extern __shared__ char smc[];
    const uint32_t smb = smem_u32(smc);
    const int tid  = threadIdx.x;
    const int warp = tid >> 5, lane = tid & 31;
    const int m0   = blockIdx.y * BM;
    const int n0   = blockIdx.x * BN;

    // staging: per stage A = 128 rows x 128B (8 cp16/thread), B same
    // thread -> row (tid>>3)+16j (j=0..7), half-col (tid&7)*8
    const __half* abase = A  + (size_t)(m0 + (tid >> 3)) * KD + ((tid & 7) << 3);
    const __half* bbase = Bt + (size_t)(n0 + (tid >> 3)) * KD + ((tid & 7) << 3);
    const uint32_t adst = smb + (uint32_t)((tid >> 3)*AH + ((tid & 7) << 3)) * 2;
    const uint32_t bdst = adst + (uint32_t)(BM*AH) * 2;

    const int wm = (warp >> 1) * 64, wn = (warp & 1) * 64;

    // A fragment lane map: m0=(r0-7,k0-7) m1=(r8-15,k0-7) m2=(r0-7,k8-15) m3=(r8-15,k8-15)
    const int arow = (lane & 7) + ((lane >> 3) & 1) * 8;
    const int akh  = (lane >> 4) * 8;
    uint32_t afrag[4];
    #pragma unroll
    for (int mt = 0; mt < 4; mt++)
        afrag[mt] = smb + (uint32_t)((wm + mt*16 + arow)*AH + akh) * 2;

    // B fragment lane map (2 n-tiles per ldsm4):
    // m0=(n0-7,k0-7) m1=(n0-7,k8-15) m2=(n8-15,k0-7) m3=(n8-15,k8-15)
    const int brow = (lane & 7) + ((lane >> 4) & 1) * 8;
    const int bkh  = ((lane >> 3) & 1) * 8;
    uint32_t bfrag[4];
    #pragma unroll
    for (int p = 0; p < 4; p++)
        bfrag[p] = smb + (uint32_t)(BM*AH + (wn + p*16 + brow)*AH + bkh) * 2;

    float acc[4][8][4];
    #pragma unroll
    for (int i = 0; i < 4; i++)
        #pragma unroll
        for (int jn = 0; jn < 8; jn++)
            #pragma unroll
            for (int q = 0; q < 4; q++) acc[i][jn][q] = 0.f;

    const int nk = KD / BK;

    // prologue: issue tiles 0, 1
    #pragma unroll
    for (int p = 0; p < 2; p++) {
        uint32_t bo = (uint32_t)p * STG_BYTES;
        #pragma unroll
        for (int j = 0; j < 8; j++)
            cp16(adst + bo + (uint32_t)(j*16*AH)*2, abase + p*BK + (size_t)j*16*KD);
        #pragma unroll
        for (int j = 0; j < 8; j++)
            cp16(bdst + bo + (uint32_t)(j*16*AH)*2, bbase + p*BK + (size_t)j*16*KD);
        CP_COMMIT();
    }

    for (int kt = 0; kt < nk; kt++) {
        CP_WAIT1();
        __syncthreads();

        const uint32_t bufo = (uint32_t)(kt & 1) * STG_BYTES;

        #pragma unroll
        for (int s = 0; s < 4; s++) {              // four k16 steps per BK=64
            const uint32_t so = bufo + (uint32_t)s * 32;   // 16 halves = 32 B
            unsigned af[4][4];
            #pragma unroll
            for (int mt = 0; mt < 4; mt++)
                ldsm4(af[mt], afrag[mt] + so);

            #pragma unroll
            for (int p = 0; p < 4; p++) {          // p covers n-tiles 2p, 2p+1
                unsigned bb[4];
                ldsm4(bb, bfrag[p] + so);
                #pragma unroll
                for (int mt = 0; mt < 4; mt++)
                    mma16(acc[mt][2*p + 0], af[mt], bb + 0);
                #pragma unroll
                for (int mt = 0; mt < 4; mt++)
                    mma16(acc[mt][2*p + 1], af[mt], bb + 2);
            }
        }

        __syncthreads();   // all warps done reading buf kt&1 before refill

        if (kt + 2 < nk) {
            uint32_t bo = (uint32_t)(kt & 1) * STG_BYTES;
            int kofs = (kt + 2) * BK;
            #pragma unroll
            for (int j = 0; j < 8; j++)
                cp16(adst + bo + (uint32_t)(j*16*AH)*2, abase + kofs + (size_t)j*16*KD);
            #pragma unroll
            for (int j = 0; j < 8; j++)
                cp16(bdst + bo + (uint32_t)(j*16*AH)*2, bbase + kofs + (size_t)j*16*KD);
        }
        CP_COMMIT();
    }

    // epilogue: bias (+gelu for PH1); PH1 -> g_h (fp16), PH2 -> scatter fp32
    #pragma unroll
    for (int mt = 0; mt < 4; mt++) {
        #pragma unroll
        for (int half = 0; half < 2; half++) {
            int row = m0 + wm + mt*16 + (lane >> 2) + half*8;
            #pragma unroll
            for (int nt = 0; nt < 8; nt++) {
                int col = n0 + wn + nt*8 + (lane & 3)*2;
                float v0 = acc[mt][nt][half*2 + 0] + bias[col];
                float v1 = acc[mt][nt][half*2 + 1] + bias[col + 1];
                if (PH1) {
                    v0 = gelu_t(v0); v1 = gelu_t(v1);
                    __half2 hv = __floats2half2_rn(v0, v1);
                    *(__half2*)(g_h + (size_t)row * ND + col) = hv;
                } else {
                    int bb2 = row >> 12;
                    size_t ob = ((size_t)(bb2*Tt + g_sel[row])) * (size_t)ND;
                    *(float2*)(Out + ob + col) = make_float2(v0, v1);
                }
            }
        }
    }
}

// ---------------------------------------------------------------------------
extern "C" void kernel_launch(void* const* d_in, const int* in_sizes, int n_in,
                              void* d_out, int out_size)
{
    const float* x  = (const float*)d_in[0];
    const float* wr = (const float*)d_in[1];
    const float* w1 = (const float*)d_in[2];
    const float* b1 = (const float*)d_in[3];
    const float* w2 = (const float*)d_in[4];
    const float* b2 = (const float*)d_in[5];
    float* out = (float*)d_out;

    __half* xh;  cudaGetSymbolAddress((void**)&xh,  g_xh);
    __half* h;   cudaGetSymbolAddress((void**)&h,   g_h);
    __half* w1t; cudaGetSymbolAddress((void**)&w1t, g_w1t);
    __half* w2t; cudaGetSymbolAddress((void**)&w2t, g_w2t);

    // order: scores+copy(1), select(2), prep(3), gemm1(4), gemm2(5)
    scores_copy_kernel<<<(Bb*Tt)/8, 256>>>(x, wr, out);
    select_kernel<<<Bb, 1024>>>();
    prep_kernel<<<MTOT + W1_TILES + W2_TILES, 256>>>(x, w1, w2);

    cudaFuncSetAttribute(gemm_fp16<Dd, Ff, true>,
                         cudaFuncAttributeMaxDynamicSharedMemorySize, SMEM_BYTES);
    cudaFuncSetAttribute(gemm_fp16<Ff, Dd, false>,
                         cudaFuncAttributeMaxDynamicSharedMemorySize, SMEM_BYTES);
    dim3 g1(Ff/BN, MTOT/BM);   // 32 x 128
    dim3 g2(Dd/BN, MTOT/BM);   //  8 x 128
    gemm_fp16<Dd, Ff, true ><<<g1, 128, SMEM_BYTES>>>(xh, w1t, b1, nullptr);
    gemm_fp16<Ff, Dd, false><<<g2, 128, SMEM_BYTES>>>(h,  w2t, b2, out);
}